// round 4
// baseline (speedup 1.0000x reference)
#include <cuda_runtime.h>
#include <cuda_bf16.h>
#include <cstdint>

// Correlation cost volume:
// out[b, 9*i+j, h, w] = (1/C) * sum_c x1[b,c,h,w] * x2[b,c,h+i-4,w+j-4]
// B=4, C=256, H=96, W=192, zero padding.

#define B_ 4
#define C_ 256
#define H_ 96
#define W_ 192
#define TH 4            // rows per block tile
#define TW 64           // cols per block tile
#define PW 8            // pixels per thread along w
#define CH 8            // channels per smem chunk
#define NCHUNK (C_ / CH)            // 32
#define X2ROWS 12                   // TH + 8
#define X2COLS 80                   // ext cols loaded: [w0-8, w0+72)
#define X2STR 82                    // stride ≡ 2 (mod 8): conflict-free LDS.64
#define X1STR 66                    // stride ≡ 2 (mod 8): conflict-free LDS.64
#define X2BUF (CH * X2ROWS * X2STR)     // 7872 floats
#define X1BUF (CH * TH * X1STR)         // 2112 floats
#define SMEM_FLOATS (2 * X2BUF + 2 * X1BUF)   // 19968 floats = 79872 B
#define NTHREADS 288    // (TW/PW)=8 wg * TH=4 r * 9 di
#define CHUNK_ELEMS (CH * H_ * W_)

typedef unsigned long long ull;

__device__ __forceinline__ void cp_async8(uint32_t dst, const float* src, int sz) {
    asm volatile("cp.async.ca.shared.global [%0], [%1], 8, %2;\n"
                 :: "r"(dst), "l"(src), "r"(sz));
}
__device__ __forceinline__ void cp_commit() {
    asm volatile("cp.async.commit_group;\n");
}
__device__ __forceinline__ void cp_wait1() {
    asm volatile("cp.async.wait_group 1;\n");
}
__device__ __forceinline__ ull lds64(uint32_t a) {
    ull v;
    asm("ld.shared.b64 %0, [%1];" : "=l"(v) : "r"(a));
    return v;
}
__device__ __forceinline__ void fma2(ull& acc, ull a, ull b) {
    asm("fma.rn.f32x2 %0, %1, %2, %0;" : "+l"(acc) : "l"(a), "l"(b));
}
__device__ __forceinline__ void mul2(ull& acc, ull s) {
    asm("mul.rn.f32x2 %0, %0, %1;" : "+l"(acc) : "l"(s));
}
// odd pair: (hi of e0, lo of e1)
__device__ __forceinline__ ull oddpair(ull e0, ull e1) {
    return (e0 >> 32) | (e1 << 32);
}

__global__ __launch_bounds__(NTHREADS, 2)
void corr_kernel(const float* __restrict__ x1,
                 const float* __restrict__ x2,
                 float* __restrict__ out) {
    extern __shared__ float smem[];
    float* sx2 = smem;                 // [2][CH][12][82]
    float* sx1 = smem + 2 * X2BUF;     // [2][CH][4][66]

    const int w0 = blockIdx.x * TW;
    const int h0 = blockIdx.y * TH;
    const int b  = blockIdx.z;

    const int tid  = threadIdx.x;
    const int di   = tid >> 5;        // warp id = row displacement 0..8
    const int lane = tid & 31;
    const int r    = lane & 3;        // row within tile 0..3
    const int wg   = lane >> 2;       // pixel group 0..7
    const int wbase = wg * PW;        // 0..56
    const int rdi  = r + di;          // x2 ext row 0..11

    const float* x1g = x1 + (size_t)b * C_ * H_ * W_;
    const float* x2g = x2 + (size_t)b * C_ * H_ * W_;

    const uint32_t sx2_u = (uint32_t)__cvta_generic_to_shared(sx2);
    const uint32_t sx1_u = (uint32_t)__cvta_generic_to_shared(sx1);

    // ---------------- loader roles (loop-invariant state) ----------------
    // x2: threads 0..191 -> half-row each (40 floats): row = t>>1, 20x 8B jobs.
    // x1: threads 192..255 -> half-row each (32 floats): 16x 8B jobs.
    const bool is_x2 = (tid < 192);
    const bool is_x1 = (tid >= 192);   // 192..255 active; 256..287 idle
    const bool x1_on = (tid >= 192) && (tid < 256);

    const float* ld_src = x2g;   // base src (chunk 0)
    uint32_t     ld_dst = sx2_u;
    uint32_t     x2mask = 0;     // bit q' = job active

    if (is_x2) {
        int row = tid >> 1;              // 0..95
        int c   = row / X2ROWS;          // 0..7
        int rr  = row - c * X2ROWS;      // 0..11
        int qb  = (tid & 1) * 20;        // q base
        int gh  = h0 + rr - 4;
        bool vh = (unsigned)gh < (unsigned)H_;
        int qlo = (w0 == 0) ? 4 : 0;
        int qhi = (200 - w0) >> 1; if (qhi > 40) qhi = 40;
        #pragma unroll
        for (int qq = 0; qq < 20; ++qq) {
            int q = qb + qq;
            if (vh && q >= qlo && q < qhi) x2mask |= (1u << qq);
        }
        int ghs = vh ? gh : 0;
        ld_src = x2g + ((size_t)c * H_ + ghs) * W_ + (w0 - 8) + 2 * qb;
        ld_dst = sx2_u + (uint32_t)(((c * X2ROWS + rr) * X2STR + 2 * qb) * 4);
    } else if (x1_on) {
        int idx  = tid - 192;            // 0..63
        int c    = idx >> 3;             // 0..7
        int rr   = (idx >> 1) & 3;       // 0..3
        int half = idx & 1;              // 0/1 -> cols [0,32) / [32,64)
        ld_src = x1g + ((size_t)c * H_ + (h0 + rr)) * W_ + w0 + half * 32;
        ld_dst = sx1_u + (uint32_t)(((c * TH + rr) * X1STR + half * 32) * 4);
    }

    // ---------------- accumulators (packed f32x2) ----------------
    ull acc[9][4];
    #pragma unroll
    for (int dj = 0; dj < 9; ++dj)
        #pragma unroll
        for (int m = 0; m < 4; ++m) acc[dj][m] = 0ull;

    // ---- issue loads for chunk 0 (buffer 0) ----
    if (is_x2) {
        #pragma unroll
        for (int qq = 0; qq < 20; ++qq)
            cp_async8(ld_dst + 8 * qq, ld_src + 2 * qq, ((x2mask >> qq) & 1) << 3);
    } else if (x1_on) {
        #pragma unroll
        for (int qq = 0; qq < 16; ++qq)
            cp_async8(ld_dst + 8 * qq, ld_src + 2 * qq, 8);
    }
    cp_commit();

    // ---------------- main pipelined loop ----------------
    for (int it = 0; it < NCHUNK; ++it) {
        if (it + 1 < NCHUNK) {
            const size_t goff = (size_t)(it + 1) * CHUNK_ELEMS;
            const uint32_t bo = ((it + 1) & 1)
                ? (uint32_t)((is_x2 ? X2BUF : X1BUF) * 4) : 0u;
            if (is_x2) {
                const float* s = ld_src + goff;
                const uint32_t d = ld_dst + bo;
                #pragma unroll
                for (int qq = 0; qq < 20; ++qq)
                    cp_async8(d + 8 * qq, s + 2 * qq, ((x2mask >> qq) & 1) << 3);
            } else if (x1_on) {
                const float* s = ld_src + goff;
                const uint32_t d = ld_dst + bo;
                #pragma unroll
                for (int qq = 0; qq < 16; ++qq)
                    cp_async8(d + 8 * qq, s + 2 * qq, 8);
            }
        }
        cp_commit();
        cp_wait1();
        __syncthreads();

        uint32_t p2 = sx2_u + (uint32_t)(((it & 1) * X2BUF + rdi * X2STR + wbase + 4) * 4);
        uint32_t p1 = sx1_u + (uint32_t)(((it & 1) * X1BUF + r * X1STR + wbase) * 4);

        #pragma unroll
        for (int c = 0; c < CH; ++c) {
            ull a0 = lds64(p1);
            ull a1 = lds64(p1 + 8);
            ull a2 = lds64(p1 + 16);
            ull a3 = lds64(p1 + 24);
            ull e0 = lds64(p2);
            ull e1 = lds64(p2 + 8);
            ull e2 = lds64(p2 + 16);
            ull e3 = lds64(p2 + 24);
            ull e4 = lds64(p2 + 32);
            ull e5 = lds64(p2 + 40);
            ull e6 = lds64(p2 + 48);
            ull e7 = lds64(p2 + 56);

            // even dj: natural pairs
            fma2(acc[0][0], a0, e0); fma2(acc[0][1], a1, e1);
            fma2(acc[0][2], a2, e2); fma2(acc[0][3], a3, e3);
            fma2(acc[2][0], a0, e1); fma2(acc[2][1], a1, e2);
            fma2(acc[2][2], a2, e3); fma2(acc[2][3], a3, e4);
            fma2(acc[4][0], a0, e2); fma2(acc[4][1], a1, e3);
            fma2(acc[4][2], a2, e4); fma2(acc[4][3], a3, e5);
            fma2(acc[6][0], a0, e3); fma2(acc[6][1], a1, e4);
            fma2(acc[6][2], a2, e5); fma2(acc[6][3], a3, e6);
            fma2(acc[8][0], a0, e4); fma2(acc[8][1], a1, e5);
            fma2(acc[8][2], a2, e6); fma2(acc[8][3], a3, e7);

            // odd dj: shifted pairs, built with short liveness
            {
                ull o0 = oddpair(e0, e1);
                ull o1 = oddpair(e1, e2);
                ull o2 = oddpair(e2, e3);
                ull o3 = oddpair(e3, e4);
                fma2(acc[1][0], a0, o0); fma2(acc[1][1], a1, o1);
                fma2(acc[1][2], a2, o2); fma2(acc[1][3], a3, o3);
                ull o4 = oddpair(e4, e5);
                fma2(acc[3][0], a0, o1); fma2(acc[3][1], a1, o2);
                fma2(acc[3][2], a2, o3); fma2(acc[3][3], a3, o4);
                ull o5 = oddpair(e5, e6);
                fma2(acc[5][0], a0, o2); fma2(acc[5][1], a1, o3);
                fma2(acc[5][2], a2, o4); fma2(acc[5][3], a3, o5);
                ull o6 = oddpair(e6, e7);
                fma2(acc[7][0], a0, o3); fma2(acc[7][1], a1, o4);
                fma2(acc[7][2], a2, o5); fma2(acc[7][3], a3, o6);
            }
            p2 += (uint32_t)(X2ROWS * X2STR * 4);
            p1 += (uint32_t)(TH * X1STR * 4);
        }
        __syncthreads();
    }

    // ---------------- epilogue ----------------
    ull scale2;
    {
        float s = 1.0f / (float)C_;
        asm("mov.b64 %0, {%1, %1};" : "=l"(scale2) : "f"(s));
    }
    #pragma unroll
    for (int dj = 0; dj < 9; ++dj) {
        const int d = di * 9 + dj;
        float* o = out + (((size_t)b * 81 + d) * H_ + (h0 + r)) * W_ + w0 + wbase;
        #pragma unroll
        for (int m = 0; m < 4; ++m) mul2(acc[dj][m], scale2);
        ulonglong2 v0 = make_ulonglong2(acc[dj][0], acc[dj][1]);
        ulonglong2 v1 = make_ulonglong2(acc[dj][2], acc[dj][3]);
        *reinterpret_cast<ulonglong2*>(o)     = v0;
        *reinterpret_cast<ulonglong2*>(o + 4) = v1;
    }
}

extern "C" void kernel_launch(void* const* d_in, const int* in_sizes, int n_in,
                              void* d_out, int out_size) {
    const float* x1 = (const float*)d_in[0];
    const float* x2 = (const float*)d_in[1];
    float* out = (float*)d_out;

    static bool attr_set = false;
    if (!attr_set) {
        cudaFuncSetAttribute(corr_kernel,
                             cudaFuncAttributeMaxDynamicSharedMemorySize,
                             SMEM_FLOATS * (int)sizeof(float));
        attr_set = true;
    }

    dim3 grid(W_ / TW, H_ / TH, B_);   // (3, 24, 4)
    corr_kernel<<<grid, NTHREADS, SMEM_FLOATS * sizeof(float)>>>(x1, x2, out);
}

// round 5
// speedup vs baseline: 1.2878x; 1.2878x over previous
#include <cuda_runtime.h>
#include <cuda_bf16.h>
#include <cstdint>

// Correlation cost volume:
// out[b, 9*i+j, h, w] = (1/C) * sum_c x1[b,c,h,w] * x2[b,c,h+i-4,w+j-4]
// B=4, C=256, H=96, W=192, zero padding.

#define B_ 4
#define C_ 256
#define H_ 96
#define W_ 192
#define HW_ (H_ * W_)
#define TH 4            // rows per block tile
#define TW 64           // cols per block tile
#define PW 8            // pixels per thread along w
#define CH 8            // channels per smem chunk
#define NCHUNK (C_ / CH)            // 32
#define X2ROWS 12                   // TH + 8
#define X2STR 82                    // floats; 41 words -> conflict-free LDS.64
#define X1STR 66                    // floats; 33 words -> conflict-free LDS.64
#define X2BUF (CH * X2ROWS * X2STR)     // 7872 floats per buffer
#define X1BUF (CH * TH * X1STR)         // 2112 floats per buffer
#define SMEM_FLOATS (2 * X2BUF + 2 * X1BUF)   // 19968 floats = 79872 B
#define NTHREADS 288    // 8 wg * 4 r * 9 di
#define CHUNK_ELEMS (CH * HW_)      // global float stride per channel-chunk
#define X2CHSTRB (X2ROWS * X2STR * 4)   // 3936 B: smem byte stride per channel
#define X2BUFB (X2BUF * 4)
#define X1BUFB (X1BUF * 4)

typedef unsigned long long ull;

__device__ __forceinline__ void cp_async8(uint32_t dst, const float* src, int sz) {
    asm volatile("cp.async.ca.shared.global [%0], [%1], 8, %2;\n"
                 :: "r"(dst), "l"(src), "r"(sz));
}
__device__ __forceinline__ void cp_commit() {
    asm volatile("cp.async.commit_group;\n");
}
__device__ __forceinline__ void cp_wait1() {
    asm volatile("cp.async.wait_group 1;\n");
}
__device__ __forceinline__ ull lds64(uint32_t a) {
    ull v;
    asm("ld.shared.b64 %0, [%1];" : "=l"(v) : "r"(a));
    return v;
}
__device__ __forceinline__ void fma2(ull& acc, ull a, ull b) {
    asm("fma.rn.f32x2 %0, %1, %2, %0;" : "+l"(acc) : "l"(a), "l"(b));
}
__device__ __forceinline__ void mul2(ull& acc, ull s) {
    asm("mul.rn.f32x2 %0, %0, %1;" : "+l"(acc) : "l"(s));
}
// odd pair: (hi of e0, lo of e1)
__device__ __forceinline__ ull oddpair(ull e0, ull e1) {
    return (e0 >> 32) | (e1 << 32);
}

__global__ __launch_bounds__(NTHREADS, 2)
void corr_kernel(const float* __restrict__ x1,
                 const float* __restrict__ x2,
                 float* __restrict__ out) {
    extern __shared__ float smem[];
    float* sx2 = smem;                 // [2][CH][12][82]
    float* sx1 = smem + 2 * X2BUF;     // [2][CH][4][66]

    const int w0 = blockIdx.x * TW;
    const int h0 = blockIdx.y * TH;
    const int b  = blockIdx.z;

    const int tid  = threadIdx.x;
    const int di   = tid >> 5;        // warp id = row displacement 0..8
    const int lane = tid & 31;
    const int r    = lane & 3;        // row within tile 0..3
    const int wg   = lane >> 2;       // pixel group 0..7
    const int wbase = wg * PW;        // 0..56
    const int rdi  = r + di;          // x2 ext row 0..11

    const float* x1g = x1 + (size_t)b * C_ * HW_;
    const float* x2g = x2 + (size_t)b * C_ * HW_;

    const uint32_t sx2_u = (uint32_t)__cvta_generic_to_shared(sx2);
    const uint32_t sx1_u = (uint32_t)__cvta_generic_to_shared(sx1);

    // ================== loader precompute (loop-invariant) ==================
    // x2: thread t owns (row0 = t/48, q = t%48). Padded rows of 48 8B jobs
    // (40 real). Per round s=0..15 row = row0 + 6*s, i.e. two alternating
    // phases: even s -> rr=row0 (chan = s/2), odd s -> rr=row0+6 (chan=(s-1)/2).
    // Consecutive lanes -> consecutive q -> contiguous 256B per instruction.
    const int row0 = tid / 48;          // 0..5
    const int qx2  = tid - row0 * 48;   // 0..47
    const bool qreal = qx2 < 40;
    const int gw = w0 - 8 + 2 * qx2;                 // even
    const bool vq = (unsigned)gw < (unsigned)W_;     // pair [gw,gw+1] in-range
    const int ghE = h0 + row0 - 4;
    const int ghO = h0 + row0 + 2;
    const bool vE = (unsigned)ghE < (unsigned)H_;
    const bool vO = (unsigned)ghO < (unsigned)H_;
    const int szE = (vq && vE) ? 8 : 0;
    const int szO = (vq && vO) ? 8 : 0;
    const int gws = vq ? gw : 0;
    const float* srcE0 = x2g + (size_t)(vE ? ghE : 0) * W_ + gws;
    const float* srcO0 = x2g + (size_t)(vO ? ghO : 0) * W_ + gws;
    const uint32_t dstE0 = sx2_u + (uint32_t)((row0 * X2STR + 2 * qx2) * 4);
    const uint32_t dstO0 = sx2_u + (uint32_t)(((row0 + 6) * X2STR + 2 * qx2) * 4);

    // x1: thread t owns (row0p = t/32, q1 = t%32); rounds u=0..3, row = row0p+9u.
    const int row0p = tid >> 5;         // 0..8
    const int q1    = tid & 31;

    // issue all loads for chunk `ck` into buffer `bb`
    auto issue_chunk = [&](int ck, int bb) {
        const int chOff = ck * CHUNK_ELEMS;
        if (qreal) {
            const float* sE = srcE0 + chOff;
            const float* sO = srcO0 + chOff;
            uint32_t dE = dstE0 + (uint32_t)bb * X2BUFB;
            uint32_t dO = dstO0 + (uint32_t)bb * X2BUFB;
            #pragma unroll
            for (int s2 = 0; s2 < 8; ++s2) {
                cp_async8(dE, sE, szE);
                cp_async8(dO, sO, szO);
                sE += HW_; sO += HW_;
                dE += X2CHSTRB; dO += X2CHSTRB;
            }
        }
        #pragma unroll
        for (int u = 0; u < 4; ++u) {
            int row = row0p + 9 * u;
            if (row < 32) {
                int c  = row >> 2;
                int rr = row & 3;
                const float* s = x1g + chOff + c * HW_ + (h0 + rr) * W_ + w0 + 2 * q1;
                uint32_t d = sx1_u + (uint32_t)bb * X1BUFB
                           + (uint32_t)((row * X1STR + 2 * q1) * 4);
                cp_async8(d, s, 8);
            }
        }
    };

    // ---------------- accumulators (packed f32x2) ----------------
    ull acc[9][4];
    #pragma unroll
    for (int dj = 0; dj < 9; ++dj)
        #pragma unroll
        for (int m = 0; m < 4; ++m) acc[dj][m] = 0ull;

    // ---- prologue: chunk 0 -> buffer 0 ----
    issue_chunk(0, 0);
    cp_commit();

    // ---------------- main pipelined loop ----------------
    for (int it = 0; it < NCHUNK; ++it) {
        if (it + 1 < NCHUNK) issue_chunk(it + 1, (it + 1) & 1);
        cp_commit();
        cp_wait1();
        __syncthreads();

        uint32_t p2 = sx2_u + (uint32_t)(((it & 1) * X2BUF + rdi * X2STR + wbase + 4) * 4);
        uint32_t p1 = sx1_u + (uint32_t)(((it & 1) * X1BUF + r * X1STR + wbase) * 4);

        #pragma unroll
        for (int c = 0; c < CH; ++c) {
            ull a0 = lds64(p1);
            ull a1 = lds64(p1 + 8);
            ull a2 = lds64(p1 + 16);
            ull a3 = lds64(p1 + 24);
            ull e0 = lds64(p2);
            ull e1 = lds64(p2 + 8);
            ull e2 = lds64(p2 + 16);
            ull e3 = lds64(p2 + 24);
            ull e4 = lds64(p2 + 32);
            ull e5 = lds64(p2 + 40);
            ull e6 = lds64(p2 + 48);
            ull e7 = lds64(p2 + 56);

            // even dj: natural pairs
            fma2(acc[0][0], a0, e0); fma2(acc[0][1], a1, e1);
            fma2(acc[0][2], a2, e2); fma2(acc[0][3], a3, e3);
            fma2(acc[2][0], a0, e1); fma2(acc[2][1], a1, e2);
            fma2(acc[2][2], a2, e3); fma2(acc[2][3], a3, e4);
            fma2(acc[4][0], a0, e2); fma2(acc[4][1], a1, e3);
            fma2(acc[4][2], a2, e4); fma2(acc[4][3], a3, e5);
            fma2(acc[6][0], a0, e3); fma2(acc[6][1], a1, e4);
            fma2(acc[6][2], a2, e5); fma2(acc[6][3], a3, e6);
            fma2(acc[8][0], a0, e4); fma2(acc[8][1], a1, e5);
            fma2(acc[8][2], a2, e6); fma2(acc[8][3], a3, e7);

            // odd dj: shifted pairs, built with short liveness
            {
                ull o0 = oddpair(e0, e1);
                ull o1 = oddpair(e1, e2);
                ull o2 = oddpair(e2, e3);
                ull o3 = oddpair(e3, e4);
                fma2(acc[1][0], a0, o0); fma2(acc[1][1], a1, o1);
                fma2(acc[1][2], a2, o2); fma2(acc[1][3], a3, o3);
                ull o4 = oddpair(e4, e5);
                fma2(acc[3][0], a0, o1); fma2(acc[3][1], a1, o2);
                fma2(acc[3][2], a2, o3); fma2(acc[3][3], a3, o4);
                ull o5 = oddpair(e5, e6);
                fma2(acc[5][0], a0, o2); fma2(acc[5][1], a1, o3);
                fma2(acc[5][2], a2, o4); fma2(acc[5][3], a3, o5);
                ull o6 = oddpair(e6, e7);
                fma2(acc[7][0], a0, o3); fma2(acc[7][1], a1, o4);
                fma2(acc[7][2], a2, o5); fma2(acc[7][3], a3, o6);
            }
            p2 += (uint32_t)(X2ROWS * X2STR * 4);
            p1 += (uint32_t)(TH * X1STR * 4);
        }
        __syncthreads();
    }

    // ---------------- epilogue ----------------
    ull scale2;
    {
        float s = 1.0f / (float)C_;
        asm("mov.b64 %0, {%1, %1};" : "=l"(scale2) : "f"(s));
    }
    #pragma unroll
    for (int dj = 0; dj < 9; ++dj) {
        const int d = di * 9 + dj;
        float* o = out + (((size_t)b * 81 + d) * H_ + (h0 + r)) * W_ + w0 + wbase;
        #pragma unroll
        for (int m = 0; m < 4; ++m) mul2(acc[dj][m], scale2);
        ulonglong2 v0 = make_ulonglong2(acc[dj][0], acc[dj][1]);
        ulonglong2 v1 = make_ulonglong2(acc[dj][2], acc[dj][3]);
        *reinterpret_cast<ulonglong2*>(o)     = v0;
        *reinterpret_cast<ulonglong2*>(o + 4) = v1;
    }
}

extern "C" void kernel_launch(void* const* d_in, const int* in_sizes, int n_in,
                              void* d_out, int out_size) {
    const float* x1 = (const float*)d_in[0];
    const float* x2 = (const float*)d_in[1];
    float* out = (float*)d_out;

    static bool attr_set = false;
    if (!attr_set) {
        cudaFuncSetAttribute(corr_kernel,
                             cudaFuncAttributeMaxDynamicSharedMemorySize,
                             SMEM_FLOATS * (int)sizeof(float));
        attr_set = true;
    }

    dim3 grid(W_ / TW, H_ / TH, B_);   // (3, 24, 4)
    corr_kernel<<<grid, NTHREADS, SMEM_FLOATS * sizeof(float)>>>(x1, x2, out);
}

// round 6
// speedup vs baseline: 2.5859x; 2.0080x over previous
#include <cuda_runtime.h>
#include <cuda_bf16.h>
#include <cstdint>

// Correlation cost volume:
// out[b, 9*i+j, h, w] = (1/C) * sum_c x1[b,c,h,w] * x2[b,c,h+i-4,w+j-4]
// B=4, C=256, H=96, W=192, 9x9 displacement grid, zero padding.
// R6 = proven R2 structure (16B cp.async double-buffer, TW=32) with the
// inner loop converted to packed fma.rn.f32x2 (FFMA2).

#define B_ 4
#define C_ 256
#define H_ 96
#define W_ 192
#define TH 4          // rows per block tile
#define TW 32         // cols per block tile
#define PW 4          // pixels per thread along w
#define CH 8          // channels per smem chunk
#define NCHUNK (C_ / CH)          // 32
#define X2ROWS 12                 // TH + 8
#define X2STR 56                  // 48 used cols [w0-8, w0+40) + 8 pad (conflict-free LDS.128)
#define X1STR 40                  // 32 used + 8 pad (conflict-free LDS.128)
#define X2BUF (CH * X2ROWS * X2STR)   // 5376 floats per buffer
#define X1BUF (CH * TH * X1STR)       // 1280 floats per buffer
#define SMEM_FLOATS (2 * X2BUF + 2 * X1BUF)   // 13312 floats = 53248 B
#define NTHREADS 288  // (TW/PW) * TH * 9 = 8*4*9
#define CHUNK_ELEMS (CH * H_ * W_)   // global float stride per channel-chunk

typedef unsigned long long ull;

__device__ __forceinline__ void cp_async16(uint32_t dst, const float* src, int sz) {
    asm volatile("cp.async.cg.shared.global [%0], [%1], 16, %2;\n"
                 :: "r"(dst), "l"(src), "r"(sz));
}
__device__ __forceinline__ void cp_commit() {
    asm volatile("cp.async.commit_group;\n");
}
__device__ __forceinline__ void cp_wait1() {
    asm volatile("cp.async.wait_group 1;\n");
}
__device__ __forceinline__ void fma2(ull& acc, ull a, ull b) {
    asm("fma.rn.f32x2 %0, %1, %2, %0;" : "+l"(acc) : "l"(a), "l"(b));
}
__device__ __forceinline__ void mul2(ull& acc, ull s) {
    asm("mul.rn.f32x2 %0, %0, %1;" : "+l"(acc) : "l"(s));
}
// odd pair: (hi of e0, lo of e1)
__device__ __forceinline__ ull oddpair(ull e0, ull e1) {
    return (e0 >> 32) | (e1 << 32);
}

__global__ __launch_bounds__(NTHREADS, 2)
void corr_kernel(const float* __restrict__ x1,
                 const float* __restrict__ x2,
                 float* __restrict__ out) {
    extern __shared__ float smem[];
    float* sx2 = smem;                 // [2][CH][12][56]
    float* sx1 = smem + 2 * X2BUF;     // [2][CH][4][40]

    const int w0 = blockIdx.x * TW;
    const int h0 = blockIdx.y * TH;
    const int b  = blockIdx.z;

    const int tid  = threadIdx.x;
    const int di   = tid >> 5;        // warp id = row displacement 0..8
    const int lane = tid & 31;
    const int r    = lane & 3;        // row within tile 0..3
    const int wg   = lane >> 2;       // pixel group 0..7
    const int wbase = wg * PW;
    const int rdi  = r + di;          // x2 ext row 0..11

    const float* x1g = x1 + (size_t)b * C_ * H_ * W_;
    const float* x2g = x2 + (size_t)b * C_ * H_ * W_;

    const uint32_t sx2_u = (uint32_t)__cvta_generic_to_shared(sx2);
    const uint32_t sx1_u = (uint32_t)__cvta_generic_to_shared(sx1);

    // ---- precompute per-thread cp.async jobs (loop-invariant, as in R2) ----
    // x2 ext tile: CH*12 rows, 12 float4 per row covering gw in [w0-8, w0+40)
    const float* x2src[4];
    uint32_t     x2dst[4];
    int          x2sz[4];
    #pragma unroll
    for (int s = 0; s < 4; ++s) {
        int qid    = tid + NTHREADS * s;        // 0..1151
        int row_id = qid / 12;                  // 0..95
        int q      = qid - row_id * 12;         // 0..11
        int c      = row_id / 12;               // 0..7
        int rr     = row_id - c * 12;           // 0..11
        int gh  = h0 + rr - 4;
        int gw0 = w0 - 8 + 4 * q;
        bool ok = ((unsigned)gh < (unsigned)H_) && (gw0 >= 0) && (gw0 <= W_ - 4);
        x2sz[s]  = ok ? 16 : 0;
        x2src[s] = ok ? (x2g + ((size_t)c * H_ + gh) * W_ + gw0) : x2g;
        x2dst[s] = sx2_u + (uint32_t)(((c * X2ROWS + rr) * X2STR + 4 * q) * 4);
    }
    // x1 tile: 256 float4 jobs, tid < 256
    const float* x1src = x1g;
    uint32_t     x1dst = 0;
    {
        int c  = tid >> 5;
        int rr = (tid >> 3) & 3;
        int q  = tid & 7;
        x1src = x1g + ((size_t)c * H_ + (h0 + rr)) * W_ + w0 + 4 * q;
        x1dst = sx1_u + (uint32_t)(((c * TH + rr) * X1STR + 4 * q) * 4);
    }
    const bool do_x1 = (tid < 256);

    // ---- accumulators: 9 dj x 2 packed pairs (pixels 0,1 / 2,3) ----
    ull acc[9][2];
    #pragma unroll
    for (int dj = 0; dj < 9; ++dj) {
        acc[dj][0] = 0ull;
        acc[dj][1] = 0ull;
    }

    // ---- prologue: load chunk 0 into buffer 0 ----
    #pragma unroll
    for (int s = 0; s < 4; ++s) cp_async16(x2dst[s], x2src[s], x2sz[s]);
    if (do_x1) cp_async16(x1dst, x1src, 16);
    cp_commit();

    // ---- main pipelined loop ----
    for (int it = 0; it < NCHUNK; ++it) {
        if (it + 1 < NCHUNK) {
            const size_t goff = (size_t)(it + 1) * CHUNK_ELEMS;
            const uint32_t bo2 = ((it + 1) & 1) ? (uint32_t)(X2BUF * 4) : 0u;
            const uint32_t bo1 = ((it + 1) & 1) ? (uint32_t)(X1BUF * 4) : 0u;
            #pragma unroll
            for (int s = 0; s < 4; ++s)
                cp_async16(x2dst[s] + bo2, x2src[s] + goff, x2sz[s]);
            if (do_x1) cp_async16(x1dst + bo1, x1src + goff, 16);
        }
        cp_commit();
        cp_wait1();          // chunk `it` resident
        __syncthreads();

        const float* cx1 = sx1 + (it & 1) * X1BUF + r * X1STR + wbase;
        const float* cx2 = sx2 + (it & 1) * X2BUF + rdi * X2STR + (wbase + 4);

        #pragma unroll
        for (int c = 0; c < CH; ++c) {
            // all 16B aligned: wbase%4==0, strides X1STR/X2STR multiples of 4
            const ulonglong2 A  = *reinterpret_cast<const ulonglong2*>(cx1 + c * (TH * X1STR));
            const ulonglong2 E0 = *reinterpret_cast<const ulonglong2*>(cx2 + c * (X2ROWS * X2STR));
            const ulonglong2 E1 = *reinterpret_cast<const ulonglong2*>(cx2 + c * (X2ROWS * X2STR) + 4);
            const ulonglong2 E2 = *reinterpret_cast<const ulonglong2*>(cx2 + c * (X2ROWS * X2STR) + 8);
            const ull a0 = A.x,  a1 = A.y;            // pixels (0,1) (2,3)
            const ull e0 = E0.x, e1 = E0.y;           // window pairs 0-1, 2-3
            const ull e2 = E1.x, e3 = E1.y;           // 4-5, 6-7
            const ull e4 = E2.x, e5 = E2.y;           // 8-9, 10-11

            // even dj: natural pairs e[dj/2 + m]
            fma2(acc[0][0], a0, e0); fma2(acc[0][1], a1, e1);
            fma2(acc[2][0], a0, e1); fma2(acc[2][1], a1, e2);
            fma2(acc[4][0], a0, e2); fma2(acc[4][1], a1, e3);
            fma2(acc[6][0], a0, e3); fma2(acc[6][1], a1, e4);
            fma2(acc[8][0], a0, e4); fma2(acc[8][1], a1, e5);

            // odd dj: shifted pairs o_k = (hi e_k, lo e_{k+1})
            {
                ull o0 = oddpair(e0, e1);
                ull o1 = oddpair(e1, e2);
                fma2(acc[1][0], a0, o0); fma2(acc[1][1], a1, o1);
                ull o2 = oddpair(e2, e3);
                fma2(acc[3][0], a0, o1); fma2(acc[3][1], a1, o2);
                ull o3 = oddpair(e3, e4);
                fma2(acc[5][0], a0, o2); fma2(acc[5][1], a1, o3);
                ull o4 = oddpair(e4, e5);
                fma2(acc[7][0], a0, o3); fma2(acc[7][1], a1, o4);
            }
        }
        __syncthreads();   // buffer (it&1) free for reuse at iter it+1
    }

    // ---- epilogue: scale by 1/C and store 16B per dj ----
    ull scale2;
    {
        float s = 1.0f / (float)C_;
        asm("mov.b64 %0, {%1, %1};" : "=l"(scale2) : "f"(s));
    }
    #pragma unroll
    for (int dj = 0; dj < 9; ++dj) {
        const int d = di * 9 + dj;
        mul2(acc[dj][0], scale2);
        mul2(acc[dj][1], scale2);
        float* o = out + (((size_t)b * 81 + d) * H_ + (h0 + r)) * W_ + w0 + wbase;
        ulonglong2 v = make_ulonglong2(acc[dj][0], acc[dj][1]);
        *reinterpret_cast<ulonglong2*>(o) = v;
    }
}

extern "C" void kernel_launch(void* const* d_in, const int* in_sizes, int n_in,
                              void* d_out, int out_size) {
    const float* x1 = (const float*)d_in[0];
    const float* x2 = (const float*)d_in[1];
    float* out = (float*)d_out;

    static bool attr_set = false;
    if (!attr_set) {
        cudaFuncSetAttribute(corr_kernel,
                             cudaFuncAttributeMaxDynamicSharedMemorySize,
                             SMEM_FLOATS * (int)sizeof(float));
        attr_set = true;
    }

    dim3 grid(W_ / TW, H_ / TH, B_);   // (6, 24, 4)
    corr_kernel<<<grid, NTHREADS, SMEM_FLOATS * sizeof(float)>>>(x1, x2, out);
}